// round 3
// baseline (speedup 1.0000x reference)
#include <cuda_runtime.h>
#include <cstdint>

// ValueLayerSlow: Pauli expectations for 16 strings on 10 qubits, real states.
//   Z ops (0..9, op o -> bit 9-o):  sum_d (-1)^{bit_b(d)} x_d^2
//   X ops (10,11,12 -> masks 512/256/128): sum_d x_d * x_{d^mask}
//   Y ops (13,14,15): exactly 0.
// One warp per state; lane t holds d = i*128 + t*4 + j (8 x float4),
// kept as packed f32x2 pairs (p01 = (x,y), p23 = (z,w)).
// All heavy math in f32x2 packed ops (sm_100a); reductions via a split-merge
// butterfly (9 shuffles for 8 sums) + a 5-stage Walsh-Hadamard for lane-bit Zs.

using ull = unsigned long long;

__device__ __forceinline__ ull mul2(ull a, ull b) {
    ull r; asm("mul.rn.f32x2 %0, %1, %2;" : "=l"(r) : "l"(a), "l"(b)); return r;
}
__device__ __forceinline__ ull add2(ull a, ull b) {
    ull r; asm("add.rn.f32x2 %0, %1, %2;" : "=l"(r) : "l"(a), "l"(b)); return r;
}
__device__ __forceinline__ ull sub2(ull a, ull b) {
    ull r; asm("sub.rn.f32x2 %0, %1, %2;" : "=l"(r) : "l"(a), "l"(b)); return r;
}
__device__ __forceinline__ ull fma2(ull a, ull b, ull c) {
    ull r; asm("fma.rn.f32x2 %0, %1, %2, %3;" : "=l"(r) : "l"(a), "l"(b), "l"(c)); return r;
}
__device__ __forceinline__ void upk(ull v, float& lo, float& hi) {
    asm("mov.b64 {%0, %1}, %2;" : "=f"(lo), "=f"(hi) : "l"(v));
}

// merge2: one butterfly stage that simultaneously reduces a and b over `bit`
// and splits their identity across the lane bit. Lanes with (lane&bit)==0 end
// holding a_L + a_{L^bit}; lanes with the bit set hold b_L + b_{L^bit}.
__device__ __forceinline__ float merge2(float a, float b, int bit, int lane) {
    bool hi = (lane & bit) != 0;
    float keep = hi ? b : a;
    float send = hi ? a : b;
    float recv = __shfl_xor_sync(0xFFFFFFFFu, send, bit);
    return keep + recv;
}

__global__ void __launch_bounds__(256)
pauli_expect_kernel(const float* __restrict__ x, float* __restrict__ out,
                    int n_states) {
    const int warp = (blockIdx.x * blockDim.x + threadIdx.x) >> 5;
    const int lane = threadIdx.x & 31;
    if (warp >= n_states) return;

    const ulonglong2* xp =
        reinterpret_cast<const ulonglong2*>(x) + (size_t)warp * 256;

    ull p01[8], p23[8];
#pragma unroll
    for (int i = 0; i < 8; i++) {
        ulonglong2 t = xp[i * 32 + lane];
        p01[i] = t.x;   // floats (d+0, d+1)
        p23[i] = t.y;   // floats (d+2, d+3)
    }

    // ---- squares (packed): R_i = (a0+a2, a1+a3), Dacc = sum_i (a0-a2, a1-a3)
    ull R[8];
    ull Dacc = 0ull;
#pragma unroll
    for (int i = 0; i < 8; i++) {
        ull s01 = mul2(p01[i], p01[i]);
        ull s23 = mul2(p23[i], p23[i]);
        R[i] = add2(s01, s23);
        Dacc = add2(Dacc, sub2(s01, s23));
    }

    // ---- packed tree over i (R_i plays the role of s_i with (lo,hi) j-split)
    ull e01 = add2(R[0], R[1]), e23 = add2(R[2], R[3]);
    ull e45 = add2(R[4], R[5]), e67 = add2(R[6], R[7]);
    ull e0123 = add2(e01, e23), e4567 = add2(e45, e67);
    ull Sp  = add2(e0123, e4567);
    ull z9p = sub2(e0123, e4567);                       // i bit2 sign
    ull z8p = sub2(add2(e01, e45), add2(e23, e67));     // i bit1 sign
    ull oev = add2(add2(R[0], R[2]), add2(R[4], R[6]));
    ull odd = add2(add2(R[1], R[3]), add2(R[5], R[7]));
    ull z7p = sub2(oev, odd);                           // i bit0 sign

    float Slo, Shi, t0, t1;
    upk(Sp, Slo, Shi);
    float S  = Slo + Shi;       // per-lane sum of squares (for WH butterfly)
    float z0 = Slo - Shi;       // op9: sign from j bit0  (a0+a2 - a1 - a3)
    upk(Dacc, t0, t1);
    float z1 = t0 + t1;         // op8: sign from j bit1  (a0+a1 - a2 - a3)
    upk(z9p, t0, t1); float z9 = t0 + t1;   // op0
    upk(z8p, t0, t1); float z8 = t0 + t1;   // op1
    upk(z7p, t0, t1); float z7 = t0 + t1;   // op2

    // ---- X dots (packed FFMA chains); each unordered pair once, x2 at store
    ull A9 = 0ull, A8 = 0ull, A7 = 0ull;
#pragma unroll
    for (int k = 0; k < 4; k++) {
        // mask 512 flips i bit2: pairs (0,4)(1,5)(2,6)(3,7)
        A9 = fma2(p01[k], p01[k + 4], A9);
        A9 = fma2(p23[k], p23[k + 4], A9);
    }
    // mask 256 flips i bit1: (0,2)(1,3)(4,6)(5,7)
    A8 = fma2(p01[0], p01[2], A8); A8 = fma2(p23[0], p23[2], A8);
    A8 = fma2(p01[1], p01[3], A8); A8 = fma2(p23[1], p23[3], A8);
    A8 = fma2(p01[4], p01[6], A8); A8 = fma2(p23[4], p23[6], A8);
    A8 = fma2(p01[5], p01[7], A8); A8 = fma2(p23[5], p23[7], A8);
    // mask 128 flips i bit0: (0,1)(2,3)(4,5)(6,7)
#pragma unroll
    for (int k = 0; k < 4; k++) {
        A7 = fma2(p01[2 * k], p01[2 * k + 1], A7);
        A7 = fma2(p23[2 * k], p23[2 * k + 1], A7);
    }
    upk(A9, t0, t1); float x9 = t0 + t1;
    upk(A8, t0, t1); float x8 = t0 + t1;
    upk(A7, t0, t1); float x7 = t0 + t1;

    // ---- merged butterfly reduction of 8 scalars (9 shuffles total).
    // Identity bits after merging: bit16 (within pair), bit8, bit4.
    float m0 = merge2(z9, z8, 16, lane);
    float m1 = merge2(z7, z1, 16, lane);
    float m2 = merge2(z0, x9, 16, lane);
    float m3 = merge2(x8, x7, 16, lane);
    float n0 = merge2(m0, m1, 8, lane);
    float n1 = merge2(m2, m3, 8, lane);
    float q  = merge2(n0, n1, 4, lane);
    q += __shfl_xor_sync(0xFFFFFFFFu, q, 2);
    q += __shfl_xor_sync(0xFFFFFFFFu, q, 1);
    // q identity: bit4=0:{bit8=0:{z9,z8 by bit16}, bit8=1:{z7,z1}}
    //             bit4=1:{bit8=0:{z0,x9},          bit8=1:{x8,x7}}

    // ---- Walsh-Hadamard over S: lane 2^k holds Z on d-bit (k+2) = op (7-k)
    float w = S;
#pragma unroll
    for (int k = 0; k < 5; k++) {
        float p = __shfl_xor_sync(0xFFFFFFFFu, w, 1 << k);
        w = (lane & (1 << k)) ? (p - w) : (p + w);
    }

    // ---- one store per lane (16 outputs incl. 3 exact zeros for Y ops)
    float* o = out + (size_t)warp * 16;
    switch (lane) {
        case 0:  o[0]  = q;          break;  // z9 group lanes 0-3
        case 17: o[1]  = q;          break;  // z8 group lanes 16-19
        case 9:  o[2]  = q;          break;  // z7 group lanes 8-11
        case 16: o[3]  = w;          break;  // WH lane 16 -> op3
        case 8:  o[4]  = w;          break;  // WH lane 8  -> op4
        case 4:  o[5]  = w;          break;  // WH lane 4  -> op5
        case 2:  o[6]  = w;          break;  // WH lane 2  -> op6
        case 1:  o[7]  = w;          break;  // WH lane 1  -> op7
        case 24: o[8]  = q;          break;  // z1 group lanes 24-27
        case 5:  o[9]  = q;          break;  // z0 group lanes 4-7
        case 20: o[10] = 2.0f * q;   break;  // x9 group lanes 20-23
        case 12: o[11] = 2.0f * q;   break;  // x8 group lanes 12-15
        case 28: o[12] = 2.0f * q;   break;  // x7 group lanes 28-31
        case 13: o[13] = 0.0f;       break;
        case 14: o[14] = 0.0f;       break;
        case 15: o[15] = 0.0f;       break;
        default: break;
    }
}

extern "C" void kernel_launch(void* const* d_in, const int* in_sizes, int n_in,
                              void* d_out, int out_size) {
    const float* x = (const float*)d_in[0];
    float* out = (float*)d_out;
    const int n_states = in_sizes[0] / 1024;     // 4096 for (8,512,1024)
    const int blocks = (n_states + 7) / 8;       // 8 warps (256 thr) per block
    pauli_expect_kernel<<<blocks, 256>>>(x, out, n_states);
}

// round 4
// speedup vs baseline: 1.1231x; 1.1231x over previous
#include <cuda_runtime.h>

// ValueLayerSlow: Pauli expectation values <psi|O|psi> for 16 Pauli strings on
// 10 qubits (dim=1024), states are REAL vectors (8*512 = 4096 states).
//
// Algebraic reduction (states real):
//   Z on bit b (ops 0..9, op o -> bit 9-o):  sum_d (-1)^{bit_b(d)} x_d^2
//   X on bit b (ops 10,11,12 -> bits 9,8,7): sum_d x_d * x_{d^mask}
//   Y ops (13,14,15): exactly 0 (real part of purely-imaginary form).
//
// One warp per state. Lane t holds elements d = i*128 + t*4 + j (8 x float4).
// R4: R2 structure (proven fastest) + 128-thread blocks for SM load balance
// (1024 blocks ~ 6.9/SM instead of 512 ~ 3.46/SM with a 4-vs-3 tail) and
// __ldcs streaming loads (zero reuse -> evict-first).

__global__ void __launch_bounds__(128)
pauli_expect_kernel(const float* __restrict__ x, float* __restrict__ out,
                    int n_states) {
    const int warp = (blockIdx.x * blockDim.x + threadIdx.x) >> 5;
    const int lane = threadIdx.x & 31;
    if (warp >= n_states) return;

    const float4* xp = reinterpret_cast<const float4*>(x) + (size_t)warp * 256;

    float4 v[8];
#pragma unroll
    for (int i = 0; i < 8; i++) v[i] = __ldcs(&xp[i * 32 + lane]);

    // ---- per-lane partials ----
    float s[8];
    float z1 = 0.f;  // op8: Z on bit1 (sign from j>>1)
    float z0 = 0.f;  // op9: Z on bit0 (sign from j&1)
#pragma unroll
    for (int i = 0; i < 8; i++) {
        float a0 = v[i].x * v[i].x;
        float a1 = v[i].y * v[i].y;
        float a2 = v[i].z * v[i].z;
        float a3 = v[i].w * v[i].w;
        float p01 = a0 + a1, p23 = a2 + a3;
        s[i] = p01 + p23;
        z1 += p01 - p23;
        z0 += (a0 - a1) + (a2 - a3);
    }

    float e01 = s[0] + s[1], e23 = s[2] + s[3];
    float e45 = s[4] + s[5], e67 = s[6] + s[7];
    float S  = (e01 + e23) + (e45 + e67);          // total sum of squares
    float z9 = (e01 + e23) - (e45 + e67);          // op0: Z bit9 (i bit2)
    float z8 = (e01 + e45) - (e23 + e67);          // op1: Z bit8 (i bit1)
    float z7 = ((s[0] + s[2]) + (s[4] + s[6]))
             - ((s[1] + s[3]) + (s[5] + s[7]));    // op2: Z bit7 (i bit0)

    // ---- X ops: register-resident pair dots (each unordered pair once, x2 later)
#define DOT4(a, b) ((a).x*(b).x + (a).y*(b).y + (a).z*(b).z + (a).w*(b).w)
    float x9 = DOT4(v[0], v[4]) + DOT4(v[1], v[5])
             + DOT4(v[2], v[6]) + DOT4(v[3], v[7]);   // mask 512 (op10)
    float x8 = DOT4(v[0], v[2]) + DOT4(v[1], v[3])
             + DOT4(v[4], v[6]) + DOT4(v[5], v[7]);   // mask 256 (op11)
    float x7 = DOT4(v[0], v[1]) + DOT4(v[2], v[3])
             + DOT4(v[4], v[5]) + DOT4(v[6], v[7]);   // mask 128 (op12)
#undef DOT4

    // ---- warp reductions (8 independent 5-stage butterflies, high ILP) ----
    const unsigned FULL = 0xFFFFFFFFu;
#pragma unroll
    for (int o = 16; o > 0; o >>= 1) {
        z9 += __shfl_xor_sync(FULL, z9, o);
        z8 += __shfl_xor_sync(FULL, z8, o);
        z7 += __shfl_xor_sync(FULL, z7, o);
        z1 += __shfl_xor_sync(FULL, z1, o);
        z0 += __shfl_xor_sync(FULL, z0, o);
        x9 += __shfl_xor_sync(FULL, x9, o);
        x8 += __shfl_xor_sync(FULL, x8, o);
        x7 += __shfl_xor_sync(FULL, x7, o);
    }

    // Walsh-Hadamard butterfly over S: after 5 stages, lane L holds
    // sum_t (-1)^{popcount(t & L)} S_t. Lane 2^k = Z on d-bit (k+2) = op (7-k).
    float w = S;
#pragma unroll
    for (int k = 0; k < 5; k++) {
        float p = __shfl_xor_sync(FULL, w, 1 << k);
        w = (lane & (1 << k)) ? (p - w) : (p + w);
    }

    float* o = out + (size_t)warp * 16;
    if (lane == 0) {
        o[0]  = z9;
        o[1]  = z8;
        o[2]  = z7;
        o[8]  = z1;
        o[9]  = z0;
        o[10] = 2.0f * x9;
        o[11] = 2.0f * x8;
        o[12] = 2.0f * x7;
        o[13] = 0.0f;
        o[14] = 0.0f;
        o[15] = 0.0f;
    }
    if (lane == 1)  o[7] = w;
    if (lane == 2)  o[6] = w;
    if (lane == 4)  o[5] = w;
    if (lane == 8)  o[4] = w;
    if (lane == 16) o[3] = w;
}

extern "C" void kernel_launch(void* const* d_in, const int* in_sizes, int n_in,
                              void* d_out, int out_size) {
    const float* x = (const float*)d_in[0];
    float* out = (float*)d_out;
    const int n_states = in_sizes[0] / 1024;     // 4096 for (8,512,1024)
    const int blocks = (n_states + 3) / 4;       // 4 warps (128 thr) per block
    pauli_expect_kernel<<<blocks, 128>>>(x, out, n_states);
}